// round 3
// baseline (speedup 1.0000x reference)
#include <cuda_runtime.h>

#define NB   8
#define IMG  256
#define HW   (IMG*IMG)
#define NPIX (NB*HW)
#define BN_N 524288.0   /* 8*256*256 */

typedef unsigned long long u64;

__device__ __forceinline__ u64 pack2(float lo, float hi) {
    u64 r;
    asm("mov.b64 %0, {%1, %2};" : "=l"(r) : "f"(lo), "f"(hi));
    return r;
}
__device__ __forceinline__ void unpack2(u64 v, float& lo, float& hi) {
    asm("mov.b64 {%0, %1}, %2;" : "=f"(lo), "=f"(hi) : "l"(v));
}
__device__ __forceinline__ void ffma2(u64& d, u64 a, u64 b) {
    asm("fma.rn.f32x2 %0, %1, %2, %0;" : "+l"(d) : "l"(a), "l"(b));
}

// ---------------- static scratch (no allocations allowed) ----------------
__device__ float  g_bufA[NB*128*HW];
__device__ float  g_bufB[NB*64*HW];
__device__ float  g_maskA[NPIX];
__device__ float  g_maskB[NPIX];
__device__ double g_sum[5*128];
__device__ double g_sq[5*128];
__device__ float  g_scale[5*128];
__device__ float  g_shift[5*128];

__global__ void zero_stats_k() {
    int i = blockIdx.x*256 + threadIdx.x;
    if (i < 5*128) { g_sum[i] = 0.0; g_sq[i] = 0.0; }
}

// ---------------- fused sparse-conv block --------------------------------
// Tile 32w x 16h, 256 threads, 2 pixels/thread packed into f32x2 lanes.
// Weights staged DUPLICATED (w,w) in smem so LDS.128 feeds FFMA2 directly.
template<int CIN, int COUT, int CO_CHUNK, int D, bool ACT>
__global__ void __launch_bounds__(256) conv_block_k(
    const float* __restrict__ x,  const float* __restrict__ m_in,
    const float* __restrict__ W,  const float* __restrict__ bias,
    const float* __restrict__ scale, const float* __restrict__ shift,
    float* __restrict__ y, float* __restrict__ m_out,
    double* __restrict__ s_sum, double* __restrict__ s_sq)
{
    constexpr int TW_PIX = 32, TH_PIX = 16;
    constexpr int TW = TW_PIX + 2*D;
    constexpr int TH = TH_PIX + 2*D;
    constexpr int ET = TW*TH;
    constexpr int CI = 8;
    constexpr int CHUNKS = COUT / CO_CHUNK;

    __shared__ float xs[CI*ET];
    __shared__ float ms[ET];
    __shared__ __align__(16) float wsh[CI*9*CO_CHUNK*2];   // duplicated pairs
    __shared__ float sred[CO_CHUNK][8];
    __shared__ float qred[CO_CHUNK][8];

    const int tid  = threadIdx.x;
    const int n    = blockIdx.z / CHUNKS;
    const int cc   = blockIdx.z % CHUNKS;
    const int co0  = cc * CO_CHUNK;
    const int y0   = blockIdx.y*TH_PIX - D;
    const int x0   = blockIdx.x*TW_PIX - D;
    const int tx   = tid & 31;
    const int trow = tid >> 5;          // rows trow and trow+8

    // mask tile (zero-padded)
    for (int e = tid; e < ET; e += 256) {
        int iy = e / TW, ix = e % TW;
        int gy = y0 + iy, gx = x0 + ix;
        float mv = 0.f;
        if (gy >= 0 && gy < IMG && gx >= 0 && gx < IMG)
            mv = m_in[n*HW + gy*IMG + gx];
        ms[e] = mv;
    }

    u64 acc[CO_CHUNK];
#pragma unroll
    for (int c = 0; c < CO_CHUNK; ++c) acc[c] = 0ull;

    for (int cb = 0; cb < CIN/CI; ++cb) {
        __syncthreads();
        // stage act(x)*mask for CI channels
        for (int e = tid; e < CI*ET; e += 256) {
            int ci = e / ET, r = e % ET;
            int iy = r / TW, ix = r % TW;
            int gy = y0 + iy, gx = x0 + ix;
            float v = 0.f;
            if (gy >= 0 && gy < IMG && gx >= 0 && gx < IMG) {
                float mv = ms[r];
                if (mv != 0.f) {
                    float raw = x[(size_t)(n*CIN + cb*CI + ci)*HW + gy*IMG + gx];
                    if (ACT) {
                        raw = scale[cb*CI + ci]*raw + shift[cb*CI + ci];
                        raw = raw >= 0.f ? raw : 0.01f*raw;
                    }
                    v = raw * mv;
                }
            }
            xs[e] = v;
        }
        // stage weights duplicated: [ci][tap][co dup2]
        for (int e = tid; e < CI*9*CO_CHUNK*2; e += 256) {
            int idx = e >> 1;
            int co  = idx % CO_CHUNK;
            int tap = (idx / CO_CHUNK) % 9;
            int ci  = idx / (9*CO_CHUNK);
            wsh[e] = W[(size_t)(co0 + co)*CIN*9 + (cb*CI + ci)*9 + tap];
        }
        __syncthreads();

#pragma unroll
        for (int ci = 0; ci < CI; ++ci) {
#pragma unroll
            for (int kh = 0; kh < 3; ++kh)
#pragma unroll
                for (int kw = 0; kw < 3; ++kw) {
                    const int tap = kh*3 + kw;
                    float xv0 = xs[ci*ET + (trow     + kh*D)*TW + tx + kw*D];
                    float xv1 = xs[ci*ET + (trow + 8 + kh*D)*TW + tx + kw*D];
                    u64 xv = pack2(xv0, xv1);
                    const ulonglong2* wp =
                        (const ulonglong2*)&wsh[(ci*9 + tap)*CO_CHUNK*2];
#pragma unroll
                    for (int c2 = 0; c2 < CO_CHUNK/2; ++c2) {
                        ulonglong2 w = wp[c2];
                        ffma2(acc[2*c2+0], xv, w.x);
                        ffma2(acc[2*c2+1], xv, w.y);
                    }
                }
        }
    }

    // epilogue: count normalization, mask maxpool, BN stats
    float inv[2];
#pragma unroll
    for (int p = 0; p < 2; ++p) {
        const int r = trow + p*8;
        float msum = 0.f, mmax = 0.f;
#pragma unroll
        for (int kh = 0; kh < 3; ++kh)
#pragma unroll
            for (int kw = 0; kw < 3; ++kw) {
                float mv = ms[(r + kh*D)*TW + tx + kw*D];
                msum += mv;
                mmax = fmaxf(mmax, mv);
            }
        inv[p] = 1.f / fmaxf((float)CIN * msum, 1e-5f);
        if (cc == 0) {
            const int gy  = blockIdx.y*TH_PIX + r;
            const int gx  = blockIdx.x*TW_PIX + tx;
            m_out[n*HW + gy*IMG + gx] = mmax;
        }
    }

    const int gy0 = blockIdx.y*TH_PIX + trow;
    const int gx  = blockIdx.x*TW_PIX + tx;
    const int pix0 = gy0*IMG + gx;

    float vsum[CO_CHUNK], vsq[CO_CHUNK];
#pragma unroll
    for (int c = 0; c < CO_CHUNK; ++c) {
        float a0, a1;
        unpack2(acc[c], a0, a1);
        float v0 = a0*inv[0] + bias[co0 + c];
        float v1 = a1*inv[1] + bias[co0 + c];
        y[(size_t)(n*COUT + co0 + c)*HW + pix0]          = v0;
        y[(size_t)(n*COUT + co0 + c)*HW + pix0 + 8*IMG]  = v1;
        vsum[c] = v0 + v1;
        vsq[c]  = v0*v0 + v1*v1;
    }

    const int lane = tid & 31, w5 = tid >> 5;
#pragma unroll
    for (int c = 0; c < CO_CHUNK; ++c) {
        float s = vsum[c], q = vsq[c];
#pragma unroll
        for (int o = 16; o > 0; o >>= 1) {
            s += __shfl_xor_sync(0xffffffffu, s, o);
            q += __shfl_xor_sync(0xffffffffu, q, o);
        }
        if (lane == 0) { sred[c][w5] = s; qred[c][w5] = q; }
    }
    __syncthreads();
    if (tid < CO_CHUNK) {
        float s = 0.f, q = 0.f;
#pragma unroll
        for (int w = 0; w < 8; ++w) { s += sred[tid][w]; q += qred[tid][w]; }
        atomicAdd(&s_sum[co0 + tid], (double)s);
        atomicAdd(&s_sq [co0 + tid], (double)q);
    }
}

// ---------------- BN fold ------------------------------------------------
__global__ void finalize_k(const double* __restrict__ s_sum,
                           const double* __restrict__ s_sq,
                           const float* __restrict__ g,
                           const float* __restrict__ be,
                           float* __restrict__ scale,
                           float* __restrict__ shift, int C)
{
    int c = threadIdx.x;
    if (c < C) {
        double mean = s_sum[c] / BN_N;
        double var  = s_sq[c] / BN_N - mean*mean;
        float  sc   = g[c] * rsqrtf((float)(var + 1e-5));
        scale[c] = sc;
        shift[c] = be[c] - (float)mean * sc;
    }
}

// ---------------- final 1x1 conv (128 -> 64), packed f32x2 ----------------
__global__ void __launch_bounds__(256) final_conv_k(
    const float* __restrict__ x, const float* __restrict__ scale,
    const float* __restrict__ shift, const float* __restrict__ Wf,
    const float* __restrict__ bf, float* __restrict__ out)
{
    __shared__ __align__(16) float wsh[128*32*2];   // duplicated pairs
    __shared__ float ssh[128], shh[128];
    const int tid = threadIdx.x;
    const int co0 = blockIdx.y * 32;
    for (int e = tid; e < 128*32*2; e += 256) {
        int idx = e >> 1;
        int ci = idx >> 5, c = idx & 31;
        wsh[e] = Wf[(co0 + c)*128 + ci];
    }
    if (tid < 128) { ssh[tid] = scale[tid]; shh[tid] = shift[tid]; }
    __syncthreads();

    int gid = blockIdx.x*256 + tid;          // 0 .. NPIX/2-1
    int n   = gid >> 15;
    int pix = (gid << 1) & (HW - 1);         // even pixel

    u64 acc[32];
#pragma unroll
    for (int c = 0; c < 32; ++c) acc[c] = 0ull;

    for (int ci = 0; ci < 128; ++ci) {
        float2 v = *(const float2*)&x[((size_t)(n*128 + ci) << 16) + pix];
        float v0 = ssh[ci]*v.x + shh[ci]; v0 = v0 >= 0.f ? v0 : 0.01f*v0;
        float v1 = ssh[ci]*v.y + shh[ci]; v1 = v1 >= 0.f ? v1 : 0.01f*v1;
        u64 xv = pack2(v0, v1);
        const ulonglong2* wp = (const ulonglong2*)&wsh[ci*64];
#pragma unroll
        for (int c2 = 0; c2 < 16; ++c2) {
            ulonglong2 w = wp[c2];
            ffma2(acc[2*c2+0], xv, w.x);
            ffma2(acc[2*c2+1], xv, w.y);
        }
    }
#pragma unroll
    for (int c = 0; c < 32; ++c) {
        float a0, a1;
        unpack2(acc[c], a0, a1);
        float2 o = make_float2(a0 + bf[co0 + c], a1 + bf[co0 + c]);
        *(float2*)&out[((size_t)(n*64 + co0 + c) << 16) + pix] = o;
    }
}

__global__ void copy_mask_k(const float* __restrict__ m, float* __restrict__ out) {
    int i = blockIdx.x*256 + threadIdx.x;
    if (i < NPIX) out[i] = m[i];
}

// ---------------- launcher ------------------------------------------------
extern "C" void kernel_launch(void* const* d_in, const int* in_sizes, int n_in,
                              void* d_out, int out_size)
{
    (void)in_sizes; (void)n_in; (void)out_size;
    const float* feat = (const float*)d_in[0];
    const float* mask = (const float*)d_in[1];
    const float* Wl[5]; const float* bl[5]; const float* gl[5]; const float* bel[5];
    for (int l = 0; l < 5; ++l) {
        Wl[l]  = (const float*)d_in[2 + 4*l];
        bl[l]  = (const float*)d_in[3 + 4*l];
        gl[l]  = (const float*)d_in[4 + 4*l];
        bel[l] = (const float*)d_in[5 + 4*l];
    }
    const float* Wf = (const float*)d_in[22];
    const float* bf = (const float*)d_in[23];
    float* out = (float*)d_out;

    float *pA, *pB, *pMA, *pMB, *pScale, *pShift;
    double *pSum, *pSq;
    cudaGetSymbolAddress((void**)&pA,     g_bufA);
    cudaGetSymbolAddress((void**)&pB,     g_bufB);
    cudaGetSymbolAddress((void**)&pMA,    g_maskA);
    cudaGetSymbolAddress((void**)&pMB,    g_maskB);
    cudaGetSymbolAddress((void**)&pSum,   g_sum);
    cudaGetSymbolAddress((void**)&pSq,    g_sq);
    cudaGetSymbolAddress((void**)&pScale, g_scale);
    cudaGetSymbolAddress((void**)&pShift, g_shift);

    zero_stats_k<<<3, 256>>>();

    dim3 blk(256);
    dim3 tiles(IMG/32, IMG/16);   // 8 x 16 tiles

    // L0: 32 -> 16, d=1
    conv_block_k<32,16,16,1,false><<<dim3(tiles.x,tiles.y, NB*1), blk>>>(
        feat, mask, Wl[0], bl[0], nullptr, nullptr,
        pA, pMA, pSum + 0*128, pSq + 0*128);
    finalize_k<<<1,128>>>(pSum+0*128, pSq+0*128, gl[0], bel[0], pScale+0*128, pShift+0*128, 16);

    // L1: 16 -> 32, d=2
    conv_block_k<16,32,32,2,true><<<dim3(tiles.x,tiles.y, NB*1), blk>>>(
        pA, pMA, Wl[1], bl[1], pScale+0*128, pShift+0*128,
        pB, pMB, pSum + 1*128, pSq + 1*128);
    finalize_k<<<1,128>>>(pSum+1*128, pSq+1*128, gl[1], bel[1], pScale+1*128, pShift+1*128, 32);

    // L2: 32 -> 64, d=1
    conv_block_k<32,64,32,1,true><<<dim3(tiles.x,tiles.y, NB*2), blk>>>(
        pB, pMB, Wl[2], bl[2], pScale+1*128, pShift+1*128,
        pA, pMA, pSum + 2*128, pSq + 2*128);
    finalize_k<<<1,128>>>(pSum+2*128, pSq+2*128, gl[2], bel[2], pScale+2*128, pShift+2*128, 64);

    // L3: 64 -> 64, d=2
    conv_block_k<64,64,32,2,true><<<dim3(tiles.x,tiles.y, NB*2), blk>>>(
        pA, pMA, Wl[3], bl[3], pScale+2*128, pShift+2*128,
        pB, pMB, pSum + 3*128, pSq + 3*128);
    finalize_k<<<1,128>>>(pSum+3*128, pSq+3*128, gl[3], bel[3], pScale+3*128, pShift+3*128, 64);

    // L4: 64 -> 128, d=1
    conv_block_k<64,128,32,1,true><<<dim3(tiles.x,tiles.y, NB*4), blk>>>(
        pB, pMB, Wl[4], bl[4], pScale+3*128, pShift+3*128,
        pA, pMA, pSum + 4*128, pSq + 4*128);
    finalize_k<<<1,128>>>(pSum+4*128, pSq+4*128, gl[4], bel[4], pScale+4*128, pShift+4*128, 128);

    // final 1x1 conv with L4 BN+leaky folded on load
    final_conv_k<<<dim3(NPIX/512, 2), blk>>>(pA, pScale+4*128, pShift+4*128, Wf, bf, out);

    // mask output appended after x
    copy_mask_k<<<NPIX/256, blk>>>(pMA, out + (size_t)NB*64*HW);
}

// round 4
// speedup vs baseline: 1.4101x; 1.4101x over previous
#include <cuda_runtime.h>

#define NB   8
#define IMG  256
#define HW   (IMG*IMG)
#define NPIX (NB*HW)
#define BN_N 524288.0   /* 8*256*256 */

typedef unsigned long long u64;

__device__ __forceinline__ u64 pack2(float lo, float hi) {
    u64 r;
    asm("mov.b64 %0, {%1, %2};" : "=l"(r) : "f"(lo), "f"(hi));
    return r;
}
__device__ __forceinline__ u64 dup2(float v) {
    u64 r;
    asm("mov.b64 %0, {%1, %1};" : "=l"(r) : "f"(v));
    return r;
}
__device__ __forceinline__ void unpack2(u64 v, float& lo, float& hi) {
    asm("mov.b64 {%0, %1}, %2;" : "=f"(lo), "=f"(hi) : "l"(v));
}
__device__ __forceinline__ void ffma2(u64& d, u64 a, u64 b) {
    asm("fma.rn.f32x2 %0, %1, %2, %0;" : "+l"(d) : "l"(a), "l"(b));
}

// ---------------- static scratch (no allocations allowed) ----------------
__device__ float  g_bufA[NB*128*HW];
__device__ float  g_bufB[NB*64*HW];
__device__ float  g_maskA[NPIX];
__device__ float  g_maskB[NPIX];
__device__ double g_sum[5*128];
__device__ double g_sq[5*128];
__device__ float  g_scale[5*128];
__device__ float  g_shift[5*128];

__global__ void zero_stats_k() {
    int i = blockIdx.x*256 + threadIdx.x;
    if (i < 5*128) { g_sum[i] = 0.0; g_sq[i] = 0.0; }
}

// ---------------- fused sparse-conv block --------------------------------
// Tile 32w x 16h, 256 threads, 2 pixels/thread. Accumulators pack TWO
// OUTPUT CHANNELS per f32x2 register; pixel value is lane-duplicated.
// Weights stay in natural [ci][tap][co] order (no duplication) so each
// LDS.128 feeds 2 FFMA2 per pixel (8 FMAs) — R2's LDS density at half
// the fma-pipe instruction count.
template<int CIN, int COUT, int CO_CHUNK, int D, bool ACT>
__global__ void __launch_bounds__(256) conv_block_k(
    const float* __restrict__ x,  const float* __restrict__ m_in,
    const float* __restrict__ W,  const float* __restrict__ bias,
    const float* __restrict__ scale, const float* __restrict__ shift,
    float* __restrict__ y, float* __restrict__ m_out,
    double* __restrict__ s_sum, double* __restrict__ s_sq)
{
    constexpr int TW_PIX = 32, TH_PIX = 16;
    constexpr int TW = TW_PIX + 2*D;
    constexpr int TH = TH_PIX + 2*D;
    constexpr int ET = TW*TH;
    constexpr int CI = 8;
    constexpr int CHUNKS = COUT / CO_CHUNK;

    __shared__ float xs[CI*ET];
    __shared__ float ms[ET];
    __shared__ __align__(16) float wsh[CI*9*CO_CHUNK];
    __shared__ float sred[CO_CHUNK][8];
    __shared__ float qred[CO_CHUNK][8];

    const int tid  = threadIdx.x;
    const int n    = blockIdx.z / CHUNKS;
    const int cc   = blockIdx.z % CHUNKS;
    const int co0  = cc * CO_CHUNK;
    const int y0   = blockIdx.y*TH_PIX - D;
    const int x0   = blockIdx.x*TW_PIX - D;
    const int tx   = tid & 31;
    const int trow = tid >> 5;          // rows trow and trow+8

    // mask tile (zero-padded)
    for (int e = tid; e < ET; e += 256) {
        int iy = e / TW, ix = e % TW;
        int gy = y0 + iy, gx = x0 + ix;
        float mv = 0.f;
        if (gy >= 0 && gy < IMG && gx >= 0 && gx < IMG)
            mv = m_in[n*HW + gy*IMG + gx];
        ms[e] = mv;
    }

    u64 acc[2][CO_CHUNK/2];   // [pixel][channel-pair]
#pragma unroll
    for (int p = 0; p < 2; ++p)
#pragma unroll
        for (int c = 0; c < CO_CHUNK/2; ++c) acc[p][c] = 0ull;

    for (int cb = 0; cb < CIN/CI; ++cb) {
        __syncthreads();
        // stage act(x)*mask for CI channels
        for (int e = tid; e < CI*ET; e += 256) {
            int ci = e / ET, r = e % ET;
            int iy = r / TW, ix = r % TW;
            int gy = y0 + iy, gx = x0 + ix;
            float v = 0.f;
            if (gy >= 0 && gy < IMG && gx >= 0 && gx < IMG) {
                float mv = ms[r];
                if (mv != 0.f) {
                    float raw = x[(size_t)(n*CIN + cb*CI + ci)*HW + gy*IMG + gx];
                    if (ACT) {
                        raw = scale[cb*CI + ci]*raw + shift[cb*CI + ci];
                        raw = raw >= 0.f ? raw : 0.01f*raw;
                    }
                    v = raw * mv;
                }
            }
            xs[e] = v;
        }
        // stage weights natural order: [ci][tap][co]
        for (int e = tid; e < CI*9*CO_CHUNK; e += 256) {
            int co  = e % CO_CHUNK;
            int tap = (e / CO_CHUNK) % 9;
            int ci  = e / (9*CO_CHUNK);
            wsh[e] = W[(size_t)(co0 + co)*CIN*9 + (cb*CI + ci)*9 + tap];
        }
        __syncthreads();

#pragma unroll
        for (int ci = 0; ci < CI; ++ci) {
#pragma unroll
            for (int kh = 0; kh < 3; ++kh)
#pragma unroll
                for (int kw = 0; kw < 3; ++kw) {
                    const int tap = kh*3 + kw;
                    u64 x0p = dup2(xs[ci*ET + (trow     + kh*D)*TW + tx + kw*D]);
                    u64 x1p = dup2(xs[ci*ET + (trow + 8 + kh*D)*TW + tx + kw*D]);
                    const ulonglong2* wp =
                        (const ulonglong2*)&wsh[(ci*9 + tap)*CO_CHUNK];
#pragma unroll
                    for (int c4 = 0; c4 < CO_CHUNK/4; ++c4) {
                        ulonglong2 w = wp[c4];   // channels 4c4..4c4+3
                        ffma2(acc[0][2*c4+0], x0p, w.x);
                        ffma2(acc[0][2*c4+1], x0p, w.y);
                        ffma2(acc[1][2*c4+0], x1p, w.x);
                        ffma2(acc[1][2*c4+1], x1p, w.y);
                    }
                }
        }
    }

    // epilogue: count normalization, mask maxpool, BN stats
    float inv[2];
#pragma unroll
    for (int p = 0; p < 2; ++p) {
        const int r = trow + p*8;
        float msum = 0.f, mmax = 0.f;
#pragma unroll
        for (int kh = 0; kh < 3; ++kh)
#pragma unroll
            for (int kw = 0; kw < 3; ++kw) {
                float mv = ms[(r + kh*D)*TW + tx + kw*D];
                msum += mv;
                mmax = fmaxf(mmax, mv);
            }
        inv[p] = 1.f / fmaxf((float)CIN * msum, 1e-5f);
        if (cc == 0) {
            const int gy  = blockIdx.y*TH_PIX + r;
            const int gx  = blockIdx.x*TW_PIX + tx;
            m_out[n*HW + gy*IMG + gx] = mmax;
        }
    }

    const int gy0 = blockIdx.y*TH_PIX + trow;
    const int gx  = blockIdx.x*TW_PIX + tx;
    const int pix0 = gy0*IMG + gx;

    float vsum[CO_CHUNK], vsq[CO_CHUNK];
#pragma unroll
    for (int c2 = 0; c2 < CO_CHUNK/2; ++c2) {
        float a00, a01, a10, a11;
        unpack2(acc[0][c2], a00, a01);   // pixel0: co=2c2, 2c2+1
        unpack2(acc[1][c2], a10, a11);   // pixel1
        float b0 = bias[co0 + 2*c2], b1 = bias[co0 + 2*c2 + 1];
        float v00 = a00*inv[0] + b0, v01 = a01*inv[0] + b1;
        float v10 = a10*inv[1] + b0, v11 = a11*inv[1] + b1;
        y[(size_t)(n*COUT + co0 + 2*c2    )*HW + pix0]         = v00;
        y[(size_t)(n*COUT + co0 + 2*c2 + 1)*HW + pix0]         = v01;
        y[(size_t)(n*COUT + co0 + 2*c2    )*HW + pix0 + 8*IMG] = v10;
        y[(size_t)(n*COUT + co0 + 2*c2 + 1)*HW + pix0 + 8*IMG] = v11;
        vsum[2*c2]   = v00 + v10;  vsq[2*c2]   = v00*v00 + v10*v10;
        vsum[2*c2+1] = v01 + v11;  vsq[2*c2+1] = v01*v01 + v11*v11;
    }

    const int lane = tid & 31, w5 = tid >> 5;
#pragma unroll
    for (int c = 0; c < CO_CHUNK; ++c) {
        float s = vsum[c], q = vsq[c];
#pragma unroll
        for (int o = 16; o > 0; o >>= 1) {
            s += __shfl_xor_sync(0xffffffffu, s, o);
            q += __shfl_xor_sync(0xffffffffu, q, o);
        }
        if (lane == 0) { sred[c][w5] = s; qred[c][w5] = q; }
    }
    __syncthreads();
    if (tid < CO_CHUNK) {
        float s = 0.f, q = 0.f;
#pragma unroll
        for (int w = 0; w < 8; ++w) { s += sred[tid][w]; q += qred[tid][w]; }
        atomicAdd(&s_sum[co0 + tid], (double)s);
        atomicAdd(&s_sq [co0 + tid], (double)q);
    }
}

// ---------------- BN fold ------------------------------------------------
__global__ void finalize_k(const double* __restrict__ s_sum,
                           const double* __restrict__ s_sq,
                           const float* __restrict__ g,
                           const float* __restrict__ be,
                           float* __restrict__ scale,
                           float* __restrict__ shift, int C)
{
    int c = threadIdx.x;
    if (c < C) {
        double mean = s_sum[c] / BN_N;
        double var  = s_sq[c] / BN_N - mean*mean;
        float  sc   = g[c] * rsqrtf((float)(var + 1e-5));
        scale[c] = sc;
        shift[c] = be[c] - (float)mean * sc;
    }
}

// ---------------- final 1x1 conv (128 -> 64), channel-packed f32x2 --------
__global__ void __launch_bounds__(256) final_conv_k(
    const float* __restrict__ x, const float* __restrict__ scale,
    const float* __restrict__ shift, const float* __restrict__ Wf,
    const float* __restrict__ bf, float* __restrict__ out)
{
    __shared__ __align__(16) float wsh[128*32];
    __shared__ float ssh[128], shh[128];
    const int tid = threadIdx.x;
    const int co0 = blockIdx.y * 32;
    for (int e = tid; e < 128*32; e += 256) {
        int ci = e >> 5, c = e & 31;
        wsh[e] = Wf[(co0 + c)*128 + ci];
    }
    if (tid < 128) { ssh[tid] = scale[tid]; shh[tid] = shift[tid]; }
    __syncthreads();

    int gid = blockIdx.x*256 + tid;          // 0 .. NPIX/2-1
    int n   = gid >> 15;
    int pix = (gid << 1) & (HW - 1);         // even pixel

    u64 acc[2][16];   // [pixel][channel-pair], 32 channels
#pragma unroll
    for (int p = 0; p < 2; ++p)
#pragma unroll
        for (int c = 0; c < 16; ++c) acc[p][c] = 0ull;

    for (int ci = 0; ci < 128; ++ci) {
        float2 v = *(const float2*)&x[((size_t)(n*128 + ci) << 16) + pix];
        float v0 = ssh[ci]*v.x + shh[ci]; v0 = v0 >= 0.f ? v0 : 0.01f*v0;
        float v1 = ssh[ci]*v.y + shh[ci]; v1 = v1 >= 0.f ? v1 : 0.01f*v1;
        u64 x0p = dup2(v0);
        u64 x1p = dup2(v1);
        const ulonglong2* wp = (const ulonglong2*)&wsh[ci*32];
#pragma unroll
        for (int c4 = 0; c4 < 8; ++c4) {
            ulonglong2 w = wp[c4];
            ffma2(acc[0][2*c4+0], x0p, w.x);
            ffma2(acc[0][2*c4+1], x0p, w.y);
            ffma2(acc[1][2*c4+0], x1p, w.x);
            ffma2(acc[1][2*c4+1], x1p, w.y);
        }
    }
#pragma unroll
    for (int c2 = 0; c2 < 16; ++c2) {
        float a00, a01, a10, a11;
        unpack2(acc[0][c2], a00, a01);
        unpack2(acc[1][c2], a10, a11);
        float b0 = bf[co0 + 2*c2], b1 = bf[co0 + 2*c2 + 1];
        *(float2*)&out[((size_t)(n*64 + co0 + 2*c2    ) << 16) + pix] =
            make_float2(a00 + b0, a10 + b0);
        *(float2*)&out[((size_t)(n*64 + co0 + 2*c2 + 1) << 16) + pix] =
            make_float2(a01 + b1, a11 + b1);
    }
}

__global__ void copy_mask_k(const float* __restrict__ m, float* __restrict__ out) {
    int i = blockIdx.x*256 + threadIdx.x;
    if (i < NPIX) out[i] = m[i];
}

// ---------------- launcher ------------------------------------------------
extern "C" void kernel_launch(void* const* d_in, const int* in_sizes, int n_in,
                              void* d_out, int out_size)
{
    (void)in_sizes; (void)n_in; (void)out_size;
    const float* feat = (const float*)d_in[0];
    const float* mask = (const float*)d_in[1];
    const float* Wl[5]; const float* bl[5]; const float* gl[5]; const float* bel[5];
    for (int l = 0; l < 5; ++l) {
        Wl[l]  = (const float*)d_in[2 + 4*l];
        bl[l]  = (const float*)d_in[3 + 4*l];
        gl[l]  = (const float*)d_in[4 + 4*l];
        bel[l] = (const float*)d_in[5 + 4*l];
    }
    const float* Wf = (const float*)d_in[22];
    const float* bf = (const float*)d_in[23];
    float* out = (float*)d_out;

    float *pA, *pB, *pMA, *pMB, *pScale, *pShift;
    double *pSum, *pSq;
    cudaGetSymbolAddress((void**)&pA,     g_bufA);
    cudaGetSymbolAddress((void**)&pB,     g_bufB);
    cudaGetSymbolAddress((void**)&pMA,    g_maskA);
    cudaGetSymbolAddress((void**)&pMB,    g_maskB);
    cudaGetSymbolAddress((void**)&pSum,   g_sum);
    cudaGetSymbolAddress((void**)&pSq,    g_sq);
    cudaGetSymbolAddress((void**)&pScale, g_scale);
    cudaGetSymbolAddress((void**)&pShift, g_shift);

    zero_stats_k<<<3, 256>>>();

    dim3 blk(256);
    dim3 tiles(IMG/32, IMG/16);   // 8 x 16 tiles

    // L0: 32 -> 16, d=1
    conv_block_k<32,16,16,1,false><<<dim3(tiles.x,tiles.y, NB*1), blk>>>(
        feat, mask, Wl[0], bl[0], nullptr, nullptr,
        pA, pMA, pSum + 0*128, pSq + 0*128);
    finalize_k<<<1,128>>>(pSum+0*128, pSq+0*128, gl[0], bel[0], pScale+0*128, pShift+0*128, 16);

    // L1: 16 -> 32, d=2
    conv_block_k<16,32,32,2,true><<<dim3(tiles.x,tiles.y, NB*1), blk>>>(
        pA, pMA, Wl[1], bl[1], pScale+0*128, pShift+0*128,
        pB, pMB, pSum + 1*128, pSq + 1*128);
    finalize_k<<<1,128>>>(pSum+1*128, pSq+1*128, gl[1], bel[1], pScale+1*128, pShift+1*128, 32);

    // L2: 32 -> 64, d=1
    conv_block_k<32,64,32,1,true><<<dim3(tiles.x,tiles.y, NB*2), blk>>>(
        pB, pMB, Wl[2], bl[2], pScale+1*128, pShift+1*128,
        pA, pMA, pSum + 2*128, pSq + 2*128);
    finalize_k<<<1,128>>>(pSum+2*128, pSq+2*128, gl[2], bel[2], pScale+2*128, pShift+2*128, 64);

    // L3: 64 -> 64, d=2
    conv_block_k<64,64,32,2,true><<<dim3(tiles.x,tiles.y, NB*2), blk>>>(
        pA, pMA, Wl[3], bl[3], pScale+2*128, pShift+2*128,
        pB, pMB, pSum + 3*128, pSq + 3*128);
    finalize_k<<<1,128>>>(pSum+3*128, pSq+3*128, gl[3], bel[3], pScale+3*128, pShift+3*128, 64);

    // L4: 64 -> 128, d=1
    conv_block_k<64,128,32,1,true><<<dim3(tiles.x,tiles.y, NB*4), blk>>>(
        pB, pMB, Wl[4], bl[4], pScale+3*128, pShift+3*128,
        pA, pMA, pSum + 4*128, pSq + 4*128);
    finalize_k<<<1,128>>>(pSum+4*128, pSq+4*128, gl[4], bel[4], pScale+4*128, pShift+4*128, 128);

    // final 1x1 conv with L4 BN+leaky folded on load
    final_conv_k<<<dim3(NPIX/512, 2), blk>>>(pA, pScale+4*128, pShift+4*128, Wf, bf, out);

    // mask output appended after x
    copy_mask_k<<<NPIX/256, blk>>>(pMA, out + (size_t)NB*64*HW);
}